// round 2
// baseline (speedup 1.0000x reference)
#include <cuda_runtime.h>
#include <math.h>

// ---------------- device scratch ----------------
__device__ float g_blur[4 * 224 * 224 * 256];   // blurred feats, layout [b][y][x][c]
__device__ float g_wp[81 * 256];                // weights repacked [k*9+tap][c]
__device__ int   g_mask_mode;                   // 0=uint8, 1=int32, 2=float32

// ---------------- mask dtype detection ----------------
__global__ void detect_mask_kernel(const unsigned* __restrict__ m) {
    int lane = threadIdx.x;  // 32 threads
    int fcount = 0, zocount = 0;
#pragma unroll
    for (int i = 0; i < 8; i++) {
        unsigned w = m[lane * 8 + i];
        if (w == 0x3f800000u) fcount++;
        if (w <= 1u) zocount++;
    }
#pragma unroll
    for (int o = 16; o; o >>= 1) {
        fcount  += __shfl_xor_sync(0xffffffffu, fcount, o);
        zocount += __shfl_xor_sync(0xffffffffu, zocount, o);
    }
    if (lane == 0) g_mask_mode = (fcount > 0) ? 2 : ((zocount == 256) ? 1 : 0);
}

// ---------------- weight repack: (9,256,3,3) -> [k*9+tap][c] ----------------
__global__ void repack_kernel(const float* __restrict__ ak) {
    int idx = blockIdx.x * 256 + threadIdx.x;  // 81 blocks * 256 = 20736
    int c  = idx & 255;
    int kt = idx >> 8;           // k*9 + tap, 0..80
    int k = kt / 9, tap = kt - k * 9;
    g_wp[idx] = ak[(k * 256 + c) * 9 + tap];
}

// ---------------- separable 5x5 gaussian blur ----------------
// reads hr [b][c][y][x], writes g_blur [b][y][x][c]
// CTA: 32 channels x 16x16 tile. smem: raw 32*20*20 + h 32*357
#define BLUR_SMEM ((12800 + 32 * 357) * 4)

__global__ void __launch_bounds__(256) blur_kernel(const float* __restrict__ hr) {
    extern __shared__ float sm[];
    float* s_raw = sm;           // [ch][20][20] -> ch*400 + r*20 + col
    float* s_h   = sm + 12800;   // [ch][21pad][17] -> ch*357 + r*17 + c

    // 1D taps (float32 path matching numpy)
    const float C = -1.4142135623730951f;
    float tb[5]; float s = 0.f;
#pragma unroll
    for (int j = 0; j < 5; j++) { float d = (float)(j - 2); tb[j] = expf(d * d * C); s += tb[j]; }
#pragma unroll
    for (int j = 0; j < 5; j++) tb[j] = tb[j] / s;

    int b = blockIdx.z, cb = blockIdx.y;
    int tx = blockIdx.x % 14, ty = blockIdx.x / 14;
    int x0 = tx * 16, y0 = ty * 16;
    int t = threadIdx.x;

    const float* hrbase = hr + (long)(b * 256 + cb * 32) * 224 * 224;
    for (int e = t; e < 12800; e += 256) {
        int ch = e / 400, rem = e - ch * 400;
        int r = rem / 20, col = rem - r * 20;
        int iy = y0 - 2 + r, ix = x0 - 2 + col;
        float v = 0.f;
        if (iy >= 0 && iy < 224 && ix >= 0 && ix < 224)
            v = hrbase[(ch * 224 + iy) * 224 + ix];
        s_raw[e] = v;
    }
    __syncthreads();

    // horizontal pass: 32ch x 20 rows x 16 cols
    for (int e = t; e < 10240; e += 256) {
        int ch = e / 320, rem = e - ch * 320;
        int r = rem >> 4, c = rem & 15;
        const float* rp = s_raw + ch * 400 + r * 20 + c;
        float v = rp[0]*tb[0] + rp[1]*tb[1] + rp[2]*tb[2] + rp[3]*tb[3] + rp[4]*tb[4];
        s_h[ch * 357 + r * 17 + c] = v;
    }
    __syncthreads();

    // vertical pass + transposed store. lane = channel -> coalesced 128B stores
    float* ob = g_blur + ((long)(b * 224 + y0) * 224 + x0) * 256 + cb * 32;
    for (int e = t; e < 8192; e += 256) {
        int ch = e & 31; int pix = e >> 5;
        int py = pix >> 4, px = pix & 15;
        const float* hp = s_h + ch * 357 + py * 17 + px;
        float v = hp[0]*tb[0] + hp[17]*tb[1] + hp[34]*tb[2] + hp[51]*tb[3] + hp[68]*tb[4];
        ob[(py * 224 + px) * 256 + ch] = v;
    }
}

// ---------------- fused logits + softmax + einsum ----------------
// CTA: one batch, 2x8 output tile, all 256 channels. 256 threads.
// thread t: p = t&15 (pixel, py=p>>3, px=p&7), cb = t>>4 (16-channel block)
//
// smem floats:
//   s_blur [85][260]  parity-split region rows:
//      even rix: row = riy*9 + rix/2        (45 rows)
//      odd  rix: row = 45 + riy*8 + (rix-1)/2 (40 rows)
//   s_wp   [81][256]  at 22100  (overlaid later by s_out [256][20])
//   s_red  [8][16][9] at 42836
//   s_logit[144]      at 43988
//   s_attn [144]      at 44132
#define FUSED_SMEM (44276 * 4)

__global__ void __launch_bounds__(256) fused_kernel(
    const void* __restrict__ maskp,
    const float* __restrict__ kbias,
    const float* __restrict__ lbias,
    float* __restrict__ out)
{
    extern __shared__ float sm[];
    float* s_blur  = sm;             // 22100
    float* s_wp    = sm + 22100;     // 20736
    float* s_out   = sm + 22100;     // overlay: 256*20 = 5120
    float* s_red   = sm + 42836;     // 1152
    float* s_logit = sm + 43988;     // 144
    float* s_attn  = sm + 44132;     // 144

    int t = threadIdx.x;
    int b = blockIdx.z;
    int x0o = blockIdx.x * 8, y0o = blockIdx.y * 2;
    int rx0 = 2 * x0o - 1, ry0 = 2 * y0o - 1;

    // load weights into smem (coalesced float4)
    {
        const float4* src = (const float4*)g_wp;
        float4* dst = (float4*)s_wp;
        for (int i = t; i < 5184; i += 256) dst[i] = src[i];
    }
    // load 5x17 blurred region, all channels, parity-split rows
    {
        int c4 = (t & 63) * 4;
        const float* gb = g_blur + (long)b * 224 * 224 * 256 + c4;
        for (int pp = t >> 6; pp < 85; pp += 4) {
            int riy = pp / 17, rix = pp - riy * 17;
            int row = (rix & 1) ? (45 + riy * 8 + (rix >> 1)) : (riy * 9 + (rix >> 1));
            int iy = ry0 + riy, ix = rx0 + rix;
            float4 v = make_float4(0.f, 0.f, 0.f, 0.f);
            if (iy >= 0 && iy < 224 && ix >= 0 && ix < 224)
                v = *(const float4*)(gb + ((long)iy * 224 + ix) * 256);
            *(float4*)(s_blur + row * 260 + c4) = v;
        }
    }
    __syncthreads();

    int p = t & 15, cb = t >> 4;
    int py = p >> 3, px = p & 7;

    // ---- phase B: logits. acc[k] over this thread's 16 channels x 9 taps ----
    float acc[9];
#pragma unroll
    for (int k = 0; k < 9; k++) acc[k] = 0.f;
    const float4* sb4 = (const float4*)s_blur;  // row stride 65 float4
    const float4* sw4 = (const float4*)s_wp;    // kt stride 64 float4

#pragma unroll 1
    for (int q = 0; q < 4; q++) {
        int c4i = cb * 4 + q;
#pragma unroll
        for (int dy = 0; dy < 3; dy++) {
            int riy = 2 * py + dy;
#pragma unroll
            for (int dx = 0; dx < 3; dx++) {
                int row = (dx & 1) ? (45 + riy * 8 + px) : (riy * 9 + px + (dx >> 1));
                float4 v = sb4[row * 65 + c4i];
                int tap = dy * 3 + dx;
#pragma unroll
                for (int k = 0; k < 9; k++) {
                    float4 w = sw4[(k * 9 + tap) * 64 + c4i];
                    acc[k] = fmaf(v.x, w.x, acc[k]);
                    acc[k] = fmaf(v.y, w.y, acc[k]);
                    acc[k] = fmaf(v.z, w.z, acc[k]);
                    acc[k] = fmaf(v.w, w.w, acc[k]);
                }
            }
        }
    }

    // ---- reduce over 16 channel-blocks: shuffle pair + smem tree ----
    int wrp = t >> 5, lane = t & 31;
#pragma unroll
    for (int k = 0; k < 9; k++) acc[k] += __shfl_xor_sync(0xffffffffu, acc[k], 16);
    if (lane < 16) {
#pragma unroll
        for (int k = 0; k < 9; k++) s_red[(wrp * 16 + p) * 9 + k] = acc[k];
    }
    __syncthreads();
    if (t < 144) {
        int pp = t / 9, k = t - pp * 9;
        float v = kbias[k];
#pragma unroll
        for (int w2 = 0; w2 < 8; w2++) v += s_red[(w2 * 16 + pp) * 9 + k];
        s_logit[t] = v;
    }
    __syncthreads();

    // ---- softmax over 9, with keep_mask and logit_bias ----
    if (t < 16) {
        int pp = t;
        int oy = y0o + (pp >> 3), ox = x0o + (pp & 7);
        int mm = g_mask_mode;
        float lg[9];
#pragma unroll
        for (int k = 0; k < 9; k++) {
            long midx = ((long)(b * 9 + k) * 112 + oy) * 112 + ox;
            bool keep;
            if (mm == 0)      keep = ((const unsigned char*)maskp)[midx] != 0;
            else if (mm == 1) keep = ((const int*)maskp)[midx] != 0;
            else              keep = ((const float*)maskp)[midx] != 0.f;
            lg[k] = (keep ? s_logit[pp * 9 + k] : 0.f) + lbias[k];
        }
        float mx = lg[0];
#pragma unroll
        for (int k = 1; k < 9; k++) mx = fmaxf(mx, lg[k]);
        float e[9]; float ssum = 0.f;
#pragma unroll
        for (int k = 0; k < 9; k++) { e[k] = expf(lg[k] - mx); ssum += e[k]; }
        float invs = 1.0f / ssum;
#pragma unroll
        for (int k = 0; k < 9; k++) s_attn[pp * 9 + k] = e[k] * invs;
    }
    __syncthreads();

    // ---- phase C: einsum out[c,p] = sum_k blur[tap(p,k)][c] * attn[p][k] ----
    {
        float a[9];
#pragma unroll
        for (int k = 0; k < 9; k++) a[k] = s_attn[p * 9 + k];
#pragma unroll
        for (int q = 0; q < 4; q++) {
            int c4i = cb * 4 + q;
            float4 o = make_float4(0.f, 0.f, 0.f, 0.f);
#pragma unroll
            for (int dy = 0; dy < 3; dy++) {
                int riy = 2 * py + dy;
#pragma unroll
                for (int dx = 0; dx < 3; dx++) {
                    int row = (dx & 1) ? (45 + riy * 8 + px) : (riy * 9 + px + (dx >> 1));
                    float4 v = sb4[row * 65 + c4i];
                    float ak = a[dy * 3 + dx];
                    o.x = fmaf(v.x, ak, o.x);
                    o.y = fmaf(v.y, ak, o.y);
                    o.z = fmaf(v.z, ak, o.z);
                    o.w = fmaf(v.w, ak, o.w);
                }
            }
            int c0 = 16 * cb + 4 * q;
            s_out[(c0 + 0) * 20 + p] = o.x;
            s_out[(c0 + 1) * 20 + p] = o.y;
            s_out[(c0 + 2) * 20 + p] = o.z;
            s_out[(c0 + 3) * 20 + p] = o.w;
        }
    }
    __syncthreads();

    // ---- transposed store: thread t = channel, 4x STG.128 ----
    {
        int c = t;
        float* ob = out + ((long)(b * 256) * 112 + y0o) * 112 + x0o;
#pragma unroll
        for (int r = 0; r < 2; r++) {
#pragma unroll
            for (int u = 0; u < 2; u++) {
                float4 v = *(float4*)(s_out + c * 20 + r * 8 + u * 4);
                *(float4*)(ob + ((long)c * 112 + r) * 112 + u * 4) = v;
            }
        }
    }
}

// ---------------- launch ----------------
extern "C" void kernel_launch(void* const* d_in, const int* in_sizes, int n_in,
                              void* d_out, int out_size) {
    const float* hr  = (const float*)d_in[0];
    const float* ak  = (const float*)d_in[1];
    const float* kb  = (const float*)d_in[2];
    const float* lb  = (const float*)d_in[3];
    const void*  msk = d_in[4];
    float* out = (float*)d_out;
    (void)in_sizes; (void)n_in; (void)out_size;

    cudaFuncSetAttribute(blur_kernel,  cudaFuncAttributeMaxDynamicSharedMemorySize, BLUR_SMEM);
    cudaFuncSetAttribute(fused_kernel, cudaFuncAttributeMaxDynamicSharedMemorySize, FUSED_SMEM);

    detect_mask_kernel<<<1, 32>>>((const unsigned*)msk);
    repack_kernel<<<81, 256>>>(ak);
    blur_kernel<<<dim3(196, 8, 4), 256, BLUR_SMEM>>>(hr);
    fused_kernel<<<dim3(14, 56, 4), 256, FUSED_SMEM>>>(msk, kb, lb, out);
}

// round 3
// speedup vs baseline: 2.2291x; 2.2291x over previous
#include <cuda_runtime.h>
#include <math.h>

// ---------------- device scratch ----------------
__device__ float g_blur[4 * 224 * 224 * 256];   // blurred feats, layout [b][y][x][c]
__device__ float g_wp[81 * 256];                // weights repacked [k*9+tap][c]
__device__ int   g_mask_mode;                   // 0=uint8, 1=int32, 2=float32

// ---------------- mask dtype detection ----------------
__global__ void detect_mask_kernel(const unsigned* __restrict__ m) {
    int lane = threadIdx.x;  // 32 threads
    int fcount = 0, zocount = 0;
#pragma unroll
    for (int i = 0; i < 8; i++) {
        unsigned w = m[lane * 8 + i];
        if (w == 0x3f800000u) fcount++;
        if (w <= 1u) zocount++;
    }
#pragma unroll
    for (int o = 16; o; o >>= 1) {
        fcount  += __shfl_xor_sync(0xffffffffu, fcount, o);
        zocount += __shfl_xor_sync(0xffffffffu, zocount, o);
    }
    if (lane == 0) g_mask_mode = (fcount > 0) ? 2 : ((zocount == 256) ? 1 : 0);
}

// ---------------- weight repack: (9,256,3,3) -> [k*9+tap][c] ----------------
__global__ void repack_kernel(const float* __restrict__ ak) {
    int idx = blockIdx.x * 256 + threadIdx.x;  // 81 blocks * 256 = 20736
    int c  = idx & 255;
    int kt = idx >> 8;           // k*9 + tap, 0..80
    int k = kt / 9, tap = kt - k * 9;
    g_wp[idx] = ak[(k * 256 + c) * 9 + tap];
}

// ---------------- separable 5x5 gaussian blur v2 ----------------
// CTA: 32 channels x 16y x 32x tile, 512 threads, vertical-first rolling pass.
// s_v: [32ch][16y][37x-pad] flat ch stride 593 (odd mod 32 -> conflict-free
// cross-channel reads in phase 2).
#define BLUR_SMEM (32 * 593 * 4)

__global__ void __launch_bounds__(512, 2) blur_kernel(const float* __restrict__ hr) {
    extern __shared__ float s_v[];

    const float C = -1.4142135623730951f;
    float tb[5]; float s = 0.f;
#pragma unroll
    for (int j = 0; j < 5; j++) { float d = (float)(j - 2); tb[j] = expf(d * d * C); s += tb[j]; }
#pragma unroll
    for (int j = 0; j < 5; j++) tb[j] = tb[j] / s;

    int b = blockIdx.z, cb = blockIdx.y;
    int tx = blockIdx.x % 7, ty = blockIdx.x / 7;
    int x0 = tx * 32, y0 = ty * 16;
    int t = threadIdx.x;

    // phase 1: vertical blur, rolling window per column. 1152 columns (32ch x 36x)
    for (int j = t; j < 1152; j += 512) {
        int ch = j / 36, lx = j - ch * 36;
        int ix = x0 - 2 + lx;
        bool vx = (ix >= 0 && ix < 224);
        const float* base = hr + ((long)(b * 256 + cb * 32 + ch) * 224) * 224 + ix;
        float w0 = 0.f, w1 = 0.f, w2 = 0.f, w3 = 0.f, w4 = 0.f;
        float* ov = s_v + ch * 593 + lx;
#pragma unroll
        for (int yy = 0; yy < 20; yy++) {
            int iy = y0 - 2 + yy;
            float v = (vx && iy >= 0 && iy < 224) ? base[iy * 224] : 0.f;
            w0 = w1; w1 = w2; w2 = w3; w3 = w4; w4 = v;
            if (yy >= 4) {
                float o = w0*tb[0] + w1*tb[1] + w2*tb[2] + w3*tb[3] + w4*tb[4];
                ov[(yy - 4) * 37] = o;
            }
        }
    }
    __syncthreads();

    // phase 2: horizontal blur + transposed store (lane = channel -> 128B stores)
    {
        int ch = t & 31, yr = t >> 5;   // yr 0..15
        const float* vp = s_v + ch * 593 + yr * 37;
        float* ob = g_blur + ((long)(b * 224 + y0 + yr) * 224 + x0) * 256 + cb * 32 + ch;
        float a0 = vp[0], a1 = vp[1], a2 = vp[2], a3 = vp[3];
#pragma unroll
        for (int x = 0; x < 32; x++) {
            float a4 = vp[x + 4];
            float o = a0*tb[0] + a1*tb[1] + a2*tb[2] + a3*tb[3] + a4*tb[4];
            ob[x * 256] = o;
            a0 = a1; a1 = a2; a2 = a3; a3 = a4;
        }
    }
}

// ---------------- fused logits + softmax + einsum v2 ----------------
// CTA: 2x8 output tile, 512 threads, weights via __ldg (L2-resident).
// s_blur: 5x17 region, parity-split rows, 85 rows x 260 floats.
//   even rix: row = riy*9 + rix/2      (45 rows)
//   odd  rix: row = 45 + riy*8 + rix/2 (40 rows)
// smem floats: s_blur 22100 | s_red 16*18=288 | s_logit 144 | s_attn 144
#define FUSED_SMEM ((22100 + 288 + 144 + 144) * 4)

__global__ void __launch_bounds__(512, 2) fused_kernel(
    const void* __restrict__ maskp,
    const float* __restrict__ kbias,
    const float* __restrict__ lbias,
    float* __restrict__ out)
{
    extern __shared__ float sm[];
    float* s_blur  = sm;             // 22100
    float* s_red   = sm + 22100;     // 288
    float* s_logit = sm + 22388;     // 144
    float* s_attn  = sm + 22532;     // 144

    int t = threadIdx.x;
    int b = blockIdx.z;
    int x0o = blockIdx.x * 8, y0o = blockIdx.y * 2;
    int rx0 = 2 * x0o - 1, ry0 = 2 * y0o - 1;

    // ---- load 5x17 blurred region (85 rows x 256ch) ----
    {
        int c4 = t & 63, rr = t >> 6;   // 8 row-streams
        const float* gb = g_blur + (long)b * 224 * 224 * 256 + c4 * 4;
        for (int row = rr; row < 85; row += 8) {
            int riy, rix;
            if (row < 45) { riy = row / 9;  rix = 2 * (row - riy * 9); }
            else { int q = row - 45; riy = q >> 3; rix = 2 * (q & 7) + 1; }
            int iy = ry0 + riy, ix = rx0 + rix;
            float4 v = make_float4(0.f, 0.f, 0.f, 0.f);
            if (iy >= 0 && iy < 224 && ix >= 0 && ix < 224)
                v = *(const float4*)(gb + ((long)iy * 224 + ix) * 256);
            *(float4*)(s_blur + row * 260 + c4 * 4) = v;
        }
    }
    __syncthreads();

    // ---- phase B: logits. thread = (c4 in 0..63, pg in 0..7), 2 pixels each ----
    {
        int c4 = t & 63, pg = t >> 6;
        int py = pg >> 2, pql = pg & 3;        // px_i = 2*pql + i
        const float4* sb4 = (const float4*)s_blur;   // row stride 65
        const float4* wp4 = (const float4*)g_wp;     // kt stride 64

        float acc[9][2];
#pragma unroll
        for (int k = 0; k < 9; k++) { acc[k][0] = 0.f; acc[k][1] = 0.f; }

#pragma unroll
        for (int dy = 0; dy < 3; dy++) {
            int riy = 2 * py + dy;
#pragma unroll
            for (int dx = 0; dx < 3; dx++) {
                int r0, r1;   // rows for pixel i=0,1 : rix = 4*pql + 2*i + dx
                if (dx & 1) { int base = 45 + riy * 8 + 2 * pql; r0 = base; r1 = base + 1; }
                else        { int base = riy * 9 + 2 * pql + (dx >> 1); r0 = base; r1 = base + 1; }
                float4 v0 = sb4[r0 * 65 + c4];
                float4 v1 = sb4[r1 * 65 + c4];
                int tap = dy * 3 + dx;
#pragma unroll
                for (int k = 0; k < 9; k++) {
                    float4 w = __ldg(&wp4[(k * 9 + tap) * 64 + c4]);
                    acc[k][0] = fmaf(v0.x, w.x, acc[k][0]);
                    acc[k][0] = fmaf(v0.y, w.y, acc[k][0]);
                    acc[k][0] = fmaf(v0.z, w.z, acc[k][0]);
                    acc[k][0] = fmaf(v0.w, w.w, acc[k][0]);
                    acc[k][1] = fmaf(v1.x, w.x, acc[k][1]);
                    acc[k][1] = fmaf(v1.y, w.y, acc[k][1]);
                    acc[k][1] = fmaf(v1.z, w.z, acc[k][1]);
                    acc[k][1] = fmaf(v1.w, w.w, acc[k][1]);
                }
            }
        }

        // warp butterfly over the 32 c4-lanes
#pragma unroll
        for (int o = 16; o; o >>= 1)
#pragma unroll
            for (int k = 0; k < 9; k++) {
                acc[k][0] += __shfl_xor_sync(0xffffffffu, acc[k][0], o);
                acc[k][1] += __shfl_xor_sync(0xffffffffu, acc[k][1], o);
            }
        int w = t >> 5, lane = t & 31;
        if (lane == 0) {
#pragma unroll
            for (int k = 0; k < 9; k++) {
                s_red[w * 18 + k * 2 + 0] = acc[k][0];
                s_red[w * 18 + k * 2 + 1] = acc[k][1];
            }
        }
    }
    __syncthreads();

    // ---- combine halves + bias -> logits ----
    if (t < 144) {
        int p = t / 9, k = t - p * 9;
        int pg = p >> 1, i = p & 1;
        float v = kbias[k] + s_red[(2 * pg) * 18 + k * 2 + i]
                           + s_red[(2 * pg + 1) * 18 + k * 2 + i];
        s_logit[p * 9 + k] = v;
    }
    __syncthreads();

    // ---- softmax over 9 with keep_mask + logit_bias ----
    if (t < 16) {
        int p = t;
        int oy = y0o + (p >> 3), ox = x0o + (p & 7);
        int mm = g_mask_mode;
        float lg[9];
#pragma unroll
        for (int k = 0; k < 9; k++) {
            long midx = ((long)(b * 9 + k) * 112 + oy) * 112 + ox;
            bool keep;
            if (mm == 0)      keep = ((const unsigned char*)maskp)[midx] != 0;
            else if (mm == 1) keep = ((const int*)maskp)[midx] != 0;
            else              keep = ((const float*)maskp)[midx] != 0.f;
            lg[k] = (keep ? s_logit[p * 9 + k] : 0.f) + lbias[k];
        }
        float mx = lg[0];
#pragma unroll
        for (int k = 1; k < 9; k++) mx = fmaxf(mx, lg[k]);
        float e[9]; float ssum = 0.f;
#pragma unroll
        for (int k = 0; k < 9; k++) { e[k] = expf(lg[k] - mx); ssum += e[k]; }
        float invs = 1.0f / ssum;
#pragma unroll
        for (int k = 0; k < 9; k++) s_attn[p * 9 + k] = e[k] * invs;
    }
    __syncthreads();

    // ---- einsum: thread = (c in 0..255, r in 0..1), 8 x-outputs each ----
    {
        int c = t & 255, r = t >> 8;
        float ox[8];
#pragma unroll
        for (int x = 0; x < 8; x++) ox[x] = 0.f;
#pragma unroll
        for (int dy = 0; dy < 3; dy++) {
            int riy = 2 * r + dy;
#pragma unroll
            for (int dx = 0; dx < 3; dx++) {
                int k = dy * 3 + dx;
#pragma unroll
                for (int x = 0; x < 8; x++) {
                    int rix = 2 * x + dx;
                    int row = (rix & 1) ? (45 + riy * 8 + (rix >> 1))
                                        : (riy * 9 + (rix >> 1));
                    float v = s_blur[row * 260 + c];
                    float a = s_attn[(r * 8 + x) * 9 + k];
                    ox[x] = fmaf(v, a, ox[x]);
                }
            }
        }
        float* ob = out + ((long)(b * 256 + c) * 112 + y0o + r) * 112 + x0o;
        *(float4*)(ob)     = make_float4(ox[0], ox[1], ox[2], ox[3]);
        *(float4*)(ob + 4) = make_float4(ox[4], ox[5], ox[6], ox[7]);
    }
}

// ---------------- launch ----------------
extern "C" void kernel_launch(void* const* d_in, const int* in_sizes, int n_in,
                              void* d_out, int out_size) {
    const float* hr  = (const float*)d_in[0];
    const float* ak  = (const float*)d_in[1];
    const float* kb  = (const float*)d_in[2];
    const float* lb  = (const float*)d_in[3];
    const void*  msk = d_in[4];
    float* out = (float*)d_out;
    (void)in_sizes; (void)n_in; (void)out_size;

    cudaFuncSetAttribute(blur_kernel,  cudaFuncAttributeMaxDynamicSharedMemorySize, BLUR_SMEM);
    cudaFuncSetAttribute(fused_kernel, cudaFuncAttributeMaxDynamicSharedMemorySize, FUSED_SMEM);

    detect_mask_kernel<<<1, 32>>>((const unsigned*)msk);
    repack_kernel<<<81, 256>>>(ak);
    blur_kernel<<<dim3(98, 8, 4), 512, BLUR_SMEM>>>(hr);
    fused_kernel<<<dim3(14, 56, 4), 512, FUSED_SMEM>>>(msk, kb, lb, out);
}